// round 1
// baseline (speedup 1.0000x reference)
#include <cuda_runtime.h>
#include <cstdint>

// Dendrite: out[b,d] = sum_{v=1..255} lin_w[v-1] * prod_{s: bit(7-s) of v} sigmoid(k*(w*x-q)) + lin_b
// Subset-product factorization: v = hi*16 + lo; hi bits -> s=0..3, lo bits -> s=4..7.
// Two batch rows per thread, packed f32x2 math throughout the dense stage.

static constexpr int B = 8192;
static constexpr int D = 32;
static constexpr int S = 8;

__device__ __forceinline__ unsigned long long fma2(unsigned long long a,
                                                   unsigned long long b,
                                                   unsigned long long c) {
    unsigned long long d;
    asm("fma.rn.f32x2 %0, %1, %2, %3;" : "=l"(d) : "l"(a), "l"(b), "l"(c));
    return d;
}
__device__ __forceinline__ unsigned long long mul2(unsigned long long a,
                                                   unsigned long long b) {
    unsigned long long d;
    asm("mul.rn.f32x2 %0, %1, %2;" : "=l"(d) : "l"(a), "l"(b));
    return d;
}
__device__ __forceinline__ unsigned long long pack2(float lo, float hi) {
    unsigned long long d;
    asm("mov.b64 %0, {%1, %2};" : "=l"(d) : "f"(lo), "f"(hi));
    return d;
}
__device__ __forceinline__ void unpack2(unsigned long long v, float& lo, float& hi) {
    asm("mov.b64 {%0, %1}, %2;" : "=f"(lo), "=f"(hi) : "l"(v));
}

__device__ __forceinline__ float fast_sigmoid(float a) {
    // 1 / (1 + exp(-a)); __expf -> MUFU.EX2, __fdividef -> MUFU.RCP + mul
    return __fdividef(1.0f, 1.0f + __expf(-a));
}

__global__ __launch_bounds__(256)
void dendrite_kernel(const float* __restrict__ x,      // [B, 1, S]
                     const float* __restrict__ k,      // [D, S]
                     const float* __restrict__ w,      // [D, S]
                     const float* __restrict__ q,      // [D, S]
                     const float* __restrict__ lin_w,  // [1, 255]
                     const float* __restrict__ lin_b,  // [1]
                     float* __restrict__ out)          // [B, 1, D] -> b*D + d
{
    // Duplicated weight table: sw2[v] = (lw, lw), sw2[0] = (0,0) for the empty subset.
    __shared__ __align__(16) unsigned long long sw2[256];
    __shared__ float sA[S][D];   // [s][d] = k*w   (conflict-free: lanes stride d)
    __shared__ float sC[S][D];   // [s][d] = -k*q

    const int tid = threadIdx.x;   // 256 threads
    {
        float t = (tid == 0) ? 0.0f : lin_w[tid - 1];
        sw2[tid] = pack2(t, t);
        // tid = d*8 + s exactly matches flat [D,S] layout
        const int dd = tid >> 3, ss = tid & 7;
        const float kk = k[tid];
        sA[ss][dd] = kk * w[tid];
        sC[ss][dd] = -kk * q[tid];
    }
    __syncthreads();

    const int lane = tid & 31;          // lane = d
    const int warp = tid >> 5;          // warp handles one batch-pair
    const int d = lane;
    const int bi = blockIdx.x * 8 + warp;   // pair index, B/2 total
    const int b0 = bi * 2;

    // Load x rows for b0 and b0+1 (8 floats each, 32B-aligned). Uniform across warp.
    const float4* xp0 = reinterpret_cast<const float4*>(x + b0 * S);
    const float4 xa0 = xp0[0], xb0 = xp0[1];
    const float4 xa1 = xp0[2], xb1 = xp0[3];
    float xs0[8] = {xa0.x, xa0.y, xa0.z, xa0.w, xb0.x, xb0.y, xb0.z, xb0.w};
    float xs1[8] = {xa1.x, xa1.y, xa1.z, xa1.w, xb1.x, xb1.y, xb1.z, xb1.w};

    // p[s] = packed (sigmoid for b0, sigmoid for b1)
    unsigned long long P[8];
#pragma unroll
    for (int s = 0; s < 8; ++s) {
        const float A = sA[s][d];
        const float C = sC[s][d];
        const float p0 = fast_sigmoid(fmaf(A, xs0[s], C));
        const float p1 = fast_sigmoid(fmaf(A, xs1[s], C));
        P[s] = pack2(p0, p1);
    }

    // Subset products. Phi over s=0..3 (hi bits), Plo over s=4..7 (lo bits).
    // bit j of lo -> s = 7-j ; bit j of hi -> s = 3-j.
    unsigned long long Plo[16], Phi[16];
    Plo[0] = pack2(1.0f, 1.0f);
    Phi[0] = Plo[0];
#define SUBSET_STEP(v, j)                                   \
    Plo[v] = mul2(Plo[(v) & ((v) - 1)], P[7 - (j)]);        \
    Phi[v] = mul2(Phi[(v) & ((v) - 1)], P[3 - (j)]);
    SUBSET_STEP(1, 0)  SUBSET_STEP(2, 1)  SUBSET_STEP(3, 0)  SUBSET_STEP(4, 2)
    SUBSET_STEP(5, 0)  SUBSET_STEP(6, 1)  SUBSET_STEP(7, 0)  SUBSET_STEP(8, 3)
    SUBSET_STEP(9, 0)  SUBSET_STEP(10, 1) SUBSET_STEP(11, 0) SUBSET_STEP(12, 2)
    SUBSET_STEP(13, 0) SUBSET_STEP(14, 1) SUBSET_STEP(15, 0)
#undef SUBSET_STEP

    // Dense 16x16 weighted bilinear: acc = sum_hi Phi[hi] * (sum_lo w2[hi,lo]*Plo[lo])
    unsigned long long acc = 0ull;  // (0.f, 0.f)
#pragma unroll
    for (int hi = 0; hi < 16; ++hi) {
        unsigned long long inner = 0ull;
        const ulonglong2* wp = reinterpret_cast<const ulonglong2*>(&sw2[hi * 16]);
#pragma unroll
        for (int l = 0; l < 8; ++l) {
            const ulonglong2 ww = wp[l];          // LDS.128: two duplicated weights
            inner = fma2(ww.x, Plo[2 * l], inner);
            inner = fma2(ww.y, Plo[2 * l + 1], inner);
        }
        acc = fma2(Phi[hi], inner, acc);
    }

    float a0, a1;
    unpack2(acc, a0, a1);
    const float bias = lin_b[0];
    out[b0 * D + d]       = a0 + bias;
    out[(b0 + 1) * D + d] = a1 + bias;
}

extern "C" void kernel_launch(void* const* d_in, const int* in_sizes, int n_in,
                              void* d_out, int out_size) {
    const float* x     = (const float*)d_in[0];
    const float* k     = (const float*)d_in[1];
    const float* w     = (const float*)d_in[2];
    const float* q     = (const float*)d_in[3];
    // d_in[4] = mask (unused: generation rule is fixed binary expansion)
    const float* lin_w = (const float*)d_in[5];
    const float* lin_b = (const float*)d_in[6];
    float* out = (float*)d_out;

    // 256 threads = 8 warps = 8 batch-pairs per block -> B/16 = 512 blocks
    dendrite_kernel<<<B / 16, 256>>>(x, k, w, q, lin_w, lin_b, out);
}

// round 2
// speedup vs baseline: 1.0208x; 1.0208x over previous
#include <cuda_runtime.h>
#include <cstdint>

// Dendrite: out[b,d] = sum_{v=1..255} lin_w[v-1] * prod_{s: bit(7-s) of v} sigmoid(k*(w*x-q)) + lin_b
// Subset-product factorization: v = hi*16 + lo; hi bits -> s=0..3, lo bits -> s=4..7.
// Two batch rows per thread, packed f32x2 math; Phi generated on the fly to cut
// register pressure; multi-accumulator dense stage to break dependency chains.

static constexpr int B = 8192;
static constexpr int D = 32;
static constexpr int S = 8;

__device__ __forceinline__ unsigned long long fma2(unsigned long long a,
                                                   unsigned long long b,
                                                   unsigned long long c) {
    unsigned long long d;
    asm("fma.rn.f32x2 %0, %1, %2, %3;" : "=l"(d) : "l"(a), "l"(b), "l"(c));
    return d;
}
__device__ __forceinline__ unsigned long long mul2(unsigned long long a,
                                                   unsigned long long b) {
    unsigned long long d;
    asm("mul.rn.f32x2 %0, %1, %2;" : "=l"(d) : "l"(a), "l"(b));
    return d;
}
__device__ __forceinline__ unsigned long long add2(unsigned long long a,
                                                   unsigned long long b) {
    unsigned long long d;
    asm("add.rn.f32x2 %0, %1, %2;" : "=l"(d) : "l"(a), "l"(b));
    return d;
}
__device__ __forceinline__ unsigned long long pack2(float lo, float hi) {
    unsigned long long d;
    asm("mov.b64 %0, {%1, %2};" : "=l"(d) : "f"(lo), "f"(hi));
    return d;
}
__device__ __forceinline__ void unpack2(unsigned long long v, float& lo, float& hi) {
    asm("mov.b64 {%0, %1}, %2;" : "=f"(lo), "=f"(hi) : "l"(v));
}

__device__ __forceinline__ float fast_sigmoid(float a) {
    // sigmoid(a) = 0.5*tanh(a/2) + 0.5  -> single MUFU.TANH
    float t;
    asm("tanh.approx.f32 %0, %1;" : "=f"(t) : "f"(0.5f * a));
    return fmaf(0.5f, t, 0.5f);
}

__global__ __launch_bounds__(256, 4)
void dendrite_kernel(const float* __restrict__ x,      // [B, 1, S]
                     const float* __restrict__ k,      // [D, S]
                     const float* __restrict__ w,      // [D, S]
                     const float* __restrict__ q,      // [D, S]
                     const float* __restrict__ lin_w,  // [1, 255]
                     const float* __restrict__ lin_b,  // [1]
                     float* __restrict__ out)          // [B, 1, D] -> b*D + d
{
    // Duplicated weight table: sw2[v] = (lw, lw), sw2[0] = (0,0) for the empty subset.
    __shared__ __align__(16) unsigned long long sw2[256];
    __shared__ float sA[S][D];   // [s][d] = k*w   (lanes stride d: conflict-free)
    __shared__ float sC[S][D];   // [s][d] = -k*q

    const int tid = threadIdx.x;   // 256 threads
    {
        float t = (tid == 0) ? 0.0f : lin_w[tid - 1];
        sw2[tid] = pack2(t, t);
        const int dd = tid >> 3, ss = tid & 7;   // tid = d*8 + s matches flat [D,S]
        const float kk = k[tid];
        sA[ss][dd] = kk * w[tid];
        sC[ss][dd] = -kk * q[tid];
    }
    __syncthreads();

    const int d = tid & 31;                   // lane = d
    const int warp = tid >> 5;                // warp handles one batch-pair
    const int b0 = (blockIdx.x * 8 + warp) * 2;

    // x rows for b0 and b0+1 (uniform across warp, broadcast LDG.128)
    const float4* xp = reinterpret_cast<const float4*>(x + b0 * S);
    const float4 xa0 = xp[0], xb0 = xp[1];
    const float4 xa1 = xp[2], xb1 = xp[3];
    float xs0[8] = {xa0.x, xa0.y, xa0.z, xa0.w, xb0.x, xb0.y, xb0.z, xb0.w};
    float xs1[8] = {xa1.x, xa1.y, xa1.z, xa1.w, xb1.x, xb1.y, xb1.z, xb1.w};

    // P[s] = packed (sigmoid b0, sigmoid b1)
    unsigned long long P[8];
#pragma unroll
    for (int s = 0; s < 8; ++s) {
        const float A = sA[s][d];
        const float C = sC[s][d];
        P[s] = pack2(fast_sigmoid(fmaf(A, xs0[s], C)),
                     fast_sigmoid(fmaf(A, xs1[s], C)));
    }

    // Plo: all 16 subset products of P[4..7] (bit j of lo -> s = 7-j)
    const unsigned long long ONE2 = pack2(1.0f, 1.0f);
    unsigned long long Plo[16];
    Plo[0] = ONE2;
#pragma unroll
    for (int v = 1; v < 16; ++v) {
        const int CTZ[16] = {0,0,1,0,2,0,1,0,3,0,1,0,2,0,1,0};
        Plo[v] = mul2(Plo[v & (v - 1)], P[7 - CTZ[v]]);
    }

    // Dense stage with on-the-fly Phi (bit j of hi -> s = 3-j), 2 rotating acc
    // chains and 2-way split inner chains for ILP.
    unsigned long long Phi[16];
    Phi[0] = ONE2;
    unsigned long long acc0 = 0ull, acc1 = 0ull;   // (0.f,0.f)
#pragma unroll
    for (int hi = 0; hi < 16; ++hi) {
        const int CTZ[16] = {0,0,1,0,2,0,1,0,3,0,1,0,2,0,1,0};
        if (hi) Phi[hi] = mul2(Phi[hi & (hi - 1)], P[3 - CTZ[hi]]);

        const ulonglong2* wp = reinterpret_cast<const ulonglong2*>(&sw2[hi * 16]);
        const ulonglong2 w0 = wp[0], w1 = wp[1], w2 = wp[2], w3 = wp[3];
        const ulonglong2 w4 = wp[4], w5 = wp[5], w6 = wp[6], w7 = wp[7];

        unsigned long long iA = mul2(w0.x, Plo[0]);
        unsigned long long iB = mul2(w0.y, Plo[1]);
        iA = fma2(w1.x, Plo[2],  iA);  iB = fma2(w1.y, Plo[3],  iB);
        iA = fma2(w2.x, Plo[4],  iA);  iB = fma2(w2.y, Plo[5],  iB);
        iA = fma2(w3.x, Plo[6],  iA);  iB = fma2(w3.y, Plo[7],  iB);
        iA = fma2(w4.x, Plo[8],  iA);  iB = fma2(w4.y, Plo[9],  iB);
        iA = fma2(w5.x, Plo[10], iA);  iB = fma2(w5.y, Plo[11], iB);
        iA = fma2(w6.x, Plo[12], iA);  iB = fma2(w6.y, Plo[13], iB);
        iA = fma2(w7.x, Plo[14], iA);  iB = fma2(w7.y, Plo[15], iB);
        const unsigned long long inner = add2(iA, iB);

        if (hi & 1) acc1 = fma2(Phi[hi], inner, acc1);
        else        acc0 = fma2(Phi[hi], inner, acc0);
    }
    const unsigned long long acc = add2(acc0, acc1);

    float a0, a1;
    unpack2(acc, a0, a1);
    const float bias = lin_b[0];
    out[b0 * D + d]       = a0 + bias;
    out[(b0 + 1) * D + d] = a1 + bias;
}

extern "C" void kernel_launch(void* const* d_in, const int* in_sizes, int n_in,
                              void* d_out, int out_size) {
    const float* x     = (const float*)d_in[0];
    const float* k     = (const float*)d_in[1];
    const float* w     = (const float*)d_in[2];
    const float* q     = (const float*)d_in[3];
    // d_in[4] = mask (unused: generation rule is fixed binary expansion)
    const float* lin_w = (const float*)d_in[5];
    const float* lin_b = (const float*)d_in[6];
    float* out = (float*)d_out;

    // 256 threads = 8 warps = 8 batch-pairs per block -> B/16 = 512 blocks
    dendrite_kernel<<<B / 16, 256>>>(x, k, w, q, lin_w, lin_b, out);
}

// round 3
// speedup vs baseline: 1.0239x; 1.0030x over previous
#include <cuda_runtime.h>
#include <cstdint>

// Dendrite: out[b,d] = sum_{v=1..255} lin_w[v-1] * prod_{s: bit(7-s) of v} sigmoid(k*(w*x-q)) + lin_b
// v = hi*16 + lo; hi bits -> s=0..3, lo bits -> s=4..7.
// Scalar version: one output (b,d) per thread, pure compiler-scheduled FFMA.

static constexpr int B = 8192;
static constexpr int D = 32;
static constexpr int S = 8;

__device__ __forceinline__ float fast_sigmoid_prehalved(float arg_half) {
    // sigmoid(a) = 0.5*tanh(a/2)+0.5 ; caller supplies a/2 directly.
    float t;
    asm("tanh.approx.f32 %0, %1;" : "=f"(t) : "f"(arg_half));
    return fmaf(0.5f, t, 0.5f);
}

__global__ __launch_bounds__(256, 5)
void dendrite_kernel(const float* __restrict__ x,      // [B, 1, S]
                     const float* __restrict__ k,      // [D, S]
                     const float* __restrict__ w,      // [D, S]
                     const float* __restrict__ q,      // [D, S]
                     const float* __restrict__ lin_w,  // [1, 255]
                     const float* __restrict__ lin_b,  // [1]
                     float* __restrict__ out)          // [B, 1, D] -> b*D + d
{
    __shared__ __align__(16) float sW[256];  // sW[hi*16+lo], sW[0]=0 (empty subset)
    __shared__ float sA[S][D];               // [s][d] = 0.5*k*w
    __shared__ float sC[S][D];               // [s][d] = -0.5*k*q

    const int tid = threadIdx.x;   // 256 threads
    {
        sW[tid] = (tid == 0) ? 0.0f : lin_w[tid - 1];
        const int dd = tid >> 3, ss = tid & 7;   // tid = d*8 + s matches flat [D,S]
        const float kh = 0.5f * k[tid];
        sA[ss][dd] = kh * w[tid];
        sC[ss][dd] = -kh * q[tid];
    }
    __syncthreads();

    const int d = tid & 31;                 // lane = d
    const int warp = tid >> 5;              // warp handles one batch row
    const int b = blockIdx.x * 8 + warp;

    // x row for b (8 floats), uniform across warp -> broadcast LDG.128
    const float4* xp = reinterpret_cast<const float4*>(x + b * S);
    const float4 xa = xp[0], xb = xp[1];
    const float xs[8] = {xa.x, xa.y, xa.z, xa.w, xb.x, xb.y, xb.z, xb.w};

    // P[s] = sigmoid(k*(w*x-q)) : 1 FFMA + 1 MUFU.TANH + 1 FFMA each
    float P[8];
#pragma unroll
    for (int s = 0; s < 8; ++s)
        P[s] = fast_sigmoid_prehalved(fmaf(sA[s][d], xs[s], sC[s][d]));

    // Plo: all 16 subset products of P[4..7] (bit j of lo -> s = 7-j)
    float Plo[16];
    Plo[0] = 1.0f;
#pragma unroll
    for (int v = 1; v < 16; ++v) {
        const int CTZ[16] = {0,0,1,0,2,0,1,0,3,0,1,0,2,0,1,0};
        Plo[v] = Plo[v & (v - 1)] * P[7 - CTZ[v]];
    }

    // Dense stage: out = sum_hi Phi[hi] * (sW[hi,:] . Plo[:])
    // Phi generated on the fly (bit j of hi -> s = 3-j).
    float Phi[16];
    Phi[0] = 1.0f;
    float acc0 = 0.0f, acc1 = 0.0f;
    const float4* W4 = reinterpret_cast<const float4*>(sW);
#pragma unroll
    for (int hi = 0; hi < 16; ++hi) {
        const int CTZ[16] = {0,0,1,0,2,0,1,0,3,0,1,0,2,0,1,0};
        if (hi) Phi[hi] = Phi[hi & (hi - 1)] * P[3 - CTZ[hi]];

        const float4 w0 = W4[hi * 4 + 0];
        const float4 w1 = W4[hi * 4 + 1];
        const float4 w2 = W4[hi * 4 + 2];
        const float4 w3 = W4[hi * 4 + 3];

        float iA = w0.x * Plo[0];
        float iB = w0.y * Plo[1];
        iA = fmaf(w0.z, Plo[2],  iA);  iB = fmaf(w0.w, Plo[3],  iB);
        iA = fmaf(w1.x, Plo[4],  iA);  iB = fmaf(w1.y, Plo[5],  iB);
        iA = fmaf(w1.z, Plo[6],  iA);  iB = fmaf(w1.w, Plo[7],  iB);
        iA = fmaf(w2.x, Plo[8],  iA);  iB = fmaf(w2.y, Plo[9],  iB);
        iA = fmaf(w2.z, Plo[10], iA);  iB = fmaf(w2.w, Plo[11], iB);
        iA = fmaf(w3.x, Plo[12], iA);  iB = fmaf(w3.y, Plo[13], iB);
        iA = fmaf(w3.z, Plo[14], iA);  iB = fmaf(w3.w, Plo[15], iB);
        const float inner = iA + iB;

        if (hi & 1) acc1 = fmaf(Phi[hi], inner, acc1);
        else        acc0 = fmaf(Phi[hi], inner, acc0);
    }

    out[b * D + d] = acc0 + acc1 + lin_b[0];
}

extern "C" void kernel_launch(void* const* d_in, const int* in_sizes, int n_in,
                              void* d_out, int out_size) {
    const float* x     = (const float*)d_in[0];
    const float* k     = (const float*)d_in[1];
    const float* w     = (const float*)d_in[2];
    const float* q     = (const float*)d_in[3];
    // d_in[4] = mask (unused: fixed binary-expansion generation rule)
    const float* lin_w = (const float*)d_in[5];
    const float* lin_b = (const float*)d_in[6];
    float* out = (float*)d_out;

    // 256 threads = 8 warps = 8 batch rows per block -> B/8 = 1024 blocks
    dendrite_kernel<<<B / 8, 256>>>(x, k, w, q, lin_w, lin_b, out);
}

// round 4
// speedup vs baseline: 1.2657x; 1.2362x over previous
#include <cuda_runtime.h>
#include <cstdint>

// Dendrite: out[b,d] = sum_{v=1..255} lin_w[v-1] * prod_{s: bit(7-s) of v} sigmoid(k*(w*x-q)) + lin_b
// v = hi*16 + lo; hi bits -> s=0..3 (via P[0..3]), lo bits -> s=4..7 (via P[4..7]).
// Register-blocked: each thread computes 4 batch rows (same d), amortizing the
// 256-entry weight stream 4x and giving 4 independent FMA chains per weight.

static constexpr int B = 8192;
static constexpr int D = 32;
static constexpr int S = 8;
static constexpr int T = 4;   // batch rows per thread

__device__ __forceinline__ float fast_sigmoid_prehalved(float arg_half) {
    // sigmoid(a) = 0.5*tanh(a/2)+0.5 ; caller supplies a/2.
    float t;
    asm("tanh.approx.f32 %0, %1;" : "=f"(t) : "f"(arg_half));
    return fmaf(0.5f, t, 0.5f);
}

__global__ __launch_bounds__(128)
void dendrite_kernel(const float* __restrict__ x,      // [B, 1, S]
                     const float* __restrict__ k,      // [D, S]
                     const float* __restrict__ w,      // [D, S]
                     const float* __restrict__ q,      // [D, S]
                     const float* __restrict__ lin_w,  // [1, 255]
                     const float* __restrict__ lin_b,  // [1]
                     float* __restrict__ out)          // [B, 1, D] -> b*D + d
{
    __shared__ __align__(16) float sW[256];  // sW[hi*16+lo], sW[0]=0
    __shared__ float sA[S][D];               // [s][d] = 0.5*k*w
    __shared__ float sC[S][D];               // [s][d] = -0.5*k*q

    const int tid = threadIdx.x;   // 128 threads
#pragma unroll
    for (int i = tid; i < 256; i += 128) {
        sW[i] = (i == 0) ? 0.0f : lin_w[i - 1];
        const int dd = i >> 3, ss = i & 7;   // i = d*8 + s matches flat [D,S]
        const float kh = 0.5f * k[i];
        sA[ss][dd] = kh * w[i];
        sC[ss][dd] = -kh * q[i];
    }
    __syncthreads();

    const int d = tid & 31;                  // lane = d
    const int warp = tid >> 5;               // 4 warps/block
    const int b0 = (blockIdx.x * 4 + warp) * T;

    // x rows b0..b0+3 (32 floats, uniform across warp -> broadcast LDG.128)
    const float4* xp = reinterpret_cast<const float4*>(x + b0 * S);
    float xs[T][8];
#pragma unroll
    for (int r = 0; r < T; ++r) {
        const float4 a = xp[2 * r], b = xp[2 * r + 1];
        xs[r][0] = a.x; xs[r][1] = a.y; xs[r][2] = a.z; xs[r][3] = a.w;
        xs[r][4] = b.x; xs[r][5] = b.y; xs[r][6] = b.z; xs[r][7] = b.w;
    }

    // P[r][s] = sigmoid(k*(w*x-q))
    float P[T][8];
#pragma unroll
    for (int s = 0; s < 8; ++s) {
        const float A = sA[s][d];
        const float C = sC[s][d];
#pragma unroll
        for (int r = 0; r < T; ++r)
            P[r][s] = fast_sigmoid_prehalved(fmaf(A, xs[r][s], C));
    }

    // Plo[r][v]: all 16 subset products of P[r][4..7] (bit j of lo -> s = 7-j)
    float Plo[T][16];
#pragma unroll
    for (int r = 0; r < T; ++r) {
        Plo[r][0] = 1.0f;
#pragma unroll
        for (int v = 1; v < 16; ++v) {
            const int CTZ[16] = {0,0,1,0,2,0,1,0,3,0,1,0,2,0,1,0};
            Plo[r][v] = Plo[r][v & (v - 1)] * P[r][7 - CTZ[v]];
        }
    }

    // Dense stage: out_r = sum_hi Phi_r[hi] * (sW[hi,:] . Plo[r][:])
    // Weights loaded once per hi, shared by all 4 rows. Phi recomputed fresh
    // (<=3 muls, compile-time selection) so only Plo stays register-resident.
    float acc0[T] = {0.f, 0.f, 0.f, 0.f};
    float acc1[T] = {0.f, 0.f, 0.f, 0.f};
    const float4* W4 = reinterpret_cast<const float4*>(sW);
#pragma unroll
    for (int hi = 0; hi < 16; ++hi) {
        const float4 w0 = W4[hi * 4 + 0];
        const float4 w1 = W4[hi * 4 + 1];
        const float4 w2 = W4[hi * 4 + 2];
        const float4 w3 = W4[hi * 4 + 3];
#pragma unroll
        for (int r = 0; r < T; ++r) {
            // bit j of hi -> s = 3-j : hi&8 -> P[0], hi&4 -> P[1], hi&2 -> P[2], hi&1 -> P[3]
            float phi = 1.0f;
            if (hi & 8) phi = P[r][0];
            if (hi & 4) phi = (hi & 8) ? phi * P[r][1] : P[r][1];
            if (hi & 2) phi = (hi & 12) ? phi * P[r][2] : P[r][2];
            if (hi & 1) phi = (hi & 14) ? phi * P[r][3] : P[r][3];

            float iA = w0.x * Plo[r][0];
            float iB = w0.y * Plo[r][1];
            iA = fmaf(w0.z, Plo[r][2],  iA);  iB = fmaf(w0.w, Plo[r][3],  iB);
            iA = fmaf(w1.x, Plo[r][4],  iA);  iB = fmaf(w1.y, Plo[r][5],  iB);
            iA = fmaf(w1.z, Plo[r][6],  iA);  iB = fmaf(w1.w, Plo[r][7],  iB);
            iA = fmaf(w2.x, Plo[r][8],  iA);  iB = fmaf(w2.y, Plo[r][9],  iB);
            iA = fmaf(w2.z, Plo[r][10], iA);  iB = fmaf(w2.w, Plo[r][11], iB);
            iA = fmaf(w3.x, Plo[r][12], iA);  iB = fmaf(w3.y, Plo[r][13], iB);
            iA = fmaf(w3.z, Plo[r][14], iA);  iB = fmaf(w3.w, Plo[r][15], iB);
            const float inner = iA + iB;

            if (hi & 1) acc1[r] = fmaf(phi, inner, acc1[r]);
            else        acc0[r] = fmaf(phi, inner, acc0[r]);
        }
    }

    const float bias = lin_b[0];
#pragma unroll
    for (int r = 0; r < T; ++r)
        out[(b0 + r) * D + d] = acc0[r] + acc1[r] + bias;
}

extern "C" void kernel_launch(void* const* d_in, const int* in_sizes, int n_in,
                              void* d_out, int out_size) {
    const float* x     = (const float*)d_in[0];
    const float* k     = (const float*)d_in[1];
    const float* w     = (const float*)d_in[2];
    const float* q     = (const float*)d_in[3];
    // d_in[4] = mask (unused: fixed binary-expansion generation rule)
    const float* lin_w = (const float*)d_in[5];
    const float* lin_b = (const float*)d_in[6];
    float* out = (float*)d_out;

    // 128 threads = 4 warps, each warp: 4 batch rows -> 16 rows/block -> 512 blocks (1 wave)
    dendrite_kernel<<<B / 16, 128>>>(x, k, w, q, lin_w, lin_b, out);
}